// round 7
// baseline (speedup 1.0000x reference)
#include <cuda_runtime.h>

// FurthestPoint sampling, B=16, N=65536, npoint=2048. sm_100a.
// 8 persistent blocks/batch, 512 thr x 16 pts/thread in registers.
// Inter-block sync: proven red.release counter + ld.acquire tight poll (warp0).
// R7 change vs R5: winner coordinates ride in the 24B slot message, removing the
// dependent global point load from the per-iteration critical path.

#define BATCHES 16
#define NPTS    65536
#define NPOINT  2048
#define NBLK    8
#define THREADS 512
#define PTS     16
#define NWARP   (THREADS / 32)

// slot: [0]=val<<32|idx  [1]=x_bits<<32|y_bits  [2]=z_bits  [3]=pad (32B aligned)
__device__ unsigned long long g_slot[BATCHES][2][NBLK][4];
__device__ unsigned           g_arrive[BATCHES];

__global__ void fps_init() {
    if (threadIdx.x < BATCHES) g_arrive[threadIdx.x] = 0u;
}

__device__ __forceinline__ unsigned ld_acquire(const unsigned* p) {
    unsigned v;
    asm volatile("ld.acquire.gpu.global.u32 %0, [%1];" : "=r"(v) : "l"(p) : "memory");
    return v;
}
__device__ __forceinline__ void red_release_add(unsigned* p, unsigned v) {
    asm volatile("red.release.gpu.global.add.u32 [%0], %1;" :: "l"(p), "r"(v) : "memory");
}
__device__ __forceinline__ unsigned long long ld_cg64(const unsigned long long* p) {
    unsigned long long v;
    asm volatile("ld.global.cg.u64 %0, [%1];" : "=l"(v) : "l"(p) : "memory");
    return v;
}
__device__ __forceinline__ void st_cg64(unsigned long long* p, unsigned long long v) {
    asm volatile("st.global.cg.u64 [%0], %1;" :: "l"(p), "l"(v) : "memory");
}
__device__ __forceinline__ void st_cg128(unsigned long long* p,
                                         unsigned long long a, unsigned long long b) {
    asm volatile("st.global.cg.v2.u64 [%0], {%1, %2};" :: "l"(p), "l"(a), "l"(b) : "memory");
}

__global__ void __launch_bounds__(THREADS, 1)
fps_kernel(const float* __restrict__ xyz, float* __restrict__ out)
{
    const int b    = blockIdx.x / NBLK;
    const int blk  = blockIdx.x - b * NBLK;
    const int t    = threadIdx.x;
    const int lane = t & 31;
    const int wid  = t >> 5;

    const float* __restrict__ base = xyz + (size_t)b * NPTS * 3;
    float* __restrict__ out_idx = out;                              // (B, NPOINT) idx as float
    float* __restrict__ out_smp = out + (size_t)BATCHES * NPOINT;   // (B, 3, NPOINT)

    __shared__ unsigned s_wv[NWARP];
    __shared__ int      s_wi[NWARP];
    __shared__ float    s_wx[NWARP], s_wy[NWARP], s_wz[NWARP];
    __shared__ float    s_p[3];

    const int pbase = (blk * THREADS + t) * PTS;
    float x[PTS], y[PTS], z[PTS], s[PTS];
#pragma unroll
    for (int k = 0; k < PTS; k++) {
        const float* q = base + (size_t)(pbase + k) * 3;
        x[k] = q[0]; y[k] = q[1]; z[k] = q[2];
        s[k] = 1e10f;
    }

    float px = base[0], py = base[1], pz = base[2];
    if (blk == 0 && t == 0) {
        out_idx[(size_t)b * NPOINT] = 0.0f;
        out_smp[((size_t)b * 3 + 0) * NPOINT] = px;
        out_smp[((size_t)b * 3 + 1) * NPOINT] = py;
        out_smp[((size_t)b * 3 + 2) * NPOINT] = pz;
    }

    unsigned* arr = &g_arrive[b];

    for (int j = 1; j < NPOINT; j++) {
        // ---- distance update (registers only) ----
#pragma unroll
        for (int k = 0; k < PTS; k++) {
            float dx = x[k] - px, dy = y[k] - py, dz = z[k] - pz;
            float d  = __fmaf_rn(dz, dz, __fmaf_rn(dy, dy, __fmul_rn(dx, dx)));
            s[k] = fminf(s[k], d);
        }
        float t0 = fmaxf(fmaxf(s[0],  s[1]),  fmaxf(s[2],  s[3]));
        float t1 = fmaxf(fmaxf(s[4],  s[5]),  fmaxf(s[6],  s[7]));
        float t2 = fmaxf(fmaxf(s[8],  s[9]),  fmaxf(s[10], s[11]));
        float t3 = fmaxf(fmaxf(s[12], s[13]), fmaxf(s[14], s[15]));
        float m  = fmaxf(fmaxf(t0, t1), fmaxf(t2, t3));

        // ---- warp argmax: redux value, lowest lane == lowest index ----
        unsigned mu   = __float_as_uint(m);
        unsigned wmax = __reduce_max_sync(0xffffffffu, mu);
        unsigned ball = __ballot_sync(0xffffffffu, mu == wmax);
        int      src  = __ffs(ball) - 1;
        float    mf   = __uint_as_float(wmax);
        int kk = 0;
#pragma unroll
        for (int k = PTS - 1; k >= 0; k--)
            if (s[k] == mf) kk = k;                    // lowest k with max
        if (lane == src) {                             // winning lane has the coords
            s_wv[wid] = wmax;  s_wi[wid] = pbase + kk;
            s_wx[wid] = x[kk]; s_wy[wid] = y[kk]; s_wz[wid] = z[kk];
        }
        __syncthreads();

        if (wid == 0) {
            // ---- block argmax over 16 warp winners (lane order == index order) ----
            const int sl = lane & (NWARP - 1);
            unsigned v    = s_wv[sl];
            unsigned bmax = __reduce_max_sync(0xffffffffu, v);
            unsigned bb   = __ballot_sync(0xffffffffu, v == bmax);
            int      bsrc = __ffs(bb) - 1;             // 0..15 (dup copies at +16)

            const int buf = j & 1;
            unsigned long long (*slot)[4] = g_slot[b][buf];
            if (lane == 0) {
                unsigned long long w0 = ((unsigned long long)bmax << 32)
                                        | (unsigned)s_wi[bsrc];
                unsigned long long w1 = ((unsigned long long)__float_as_uint(s_wx[bsrc]) << 32)
                                        | __float_as_uint(s_wy[bsrc]);
                unsigned long long w2 = (unsigned long long)__float_as_uint(s_wz[bsrc]);
                st_cg128(&slot[blk][0], w0, w1);
                st_cg64(&slot[blk][2], w2);
                red_release_add(arr, 1u);   // release orders the slot stores
            }

            // ---- tight poll (warp-uniform broadcast load, 8 warps/batch) ----
            const unsigned target = (unsigned)j * NBLK;
            while (ld_acquire(arr) < target) {}

            // ---- lane i gathers slot i&7 fully (one RT), cross-block argmax ----
            const int si = lane & (NBLK - 1);
            unsigned long long r0 = ld_cg64(&slot[si][0]);
            unsigned long long r1 = ld_cg64(&slot[si][1]);
            unsigned long long r2 = ld_cg64(&slot[si][2]);
            unsigned val  = (unsigned)(r0 >> 32);
            unsigned gmax = __reduce_max_sync(0xffffffffu, val);
            unsigned key  = (val == gmax) ? ~(unsigned)r0 : 0u;  // max key == lowest idx
            unsigned gkey = __reduce_max_sync(0xffffffffu, key);
            unsigned gb   = __ballot_sync(0xffffffffu, key == gkey);
            int      gsrc = __ffs(gb) - 1;
            unsigned long long u0 = __shfl_sync(0xffffffffu, r0, gsrc);
            unsigned long long u1 = __shfl_sync(0xffffffffu, r1, gsrc);
            unsigned long long u2 = __shfl_sync(0xffffffffu, r2, gsrc);
            float nx = __uint_as_float((unsigned)(u1 >> 32));
            float ny = __uint_as_float((unsigned)u1);
            float nz = __uint_as_float((unsigned)u2);

            if (lane == 0) {
                s_p[0] = nx; s_p[1] = ny; s_p[2] = nz;
                if (blk == 0) {
                    out_idx[(size_t)b * NPOINT + j] = (float)(unsigned)u0;
                    out_smp[((size_t)b * 3 + 0) * NPOINT + j] = nx;
                    out_smp[((size_t)b * 3 + 1) * NPOINT + j] = ny;
                    out_smp[((size_t)b * 3 + 2) * NPOINT + j] = nz;
                }
            }
        }
        __syncthreads();
        px = s_p[0]; py = s_p[1]; pz = s_p[2];
    }
}

extern "C" void kernel_launch(void* const* d_in, const int* in_sizes, int n_in,
                              void* d_out, int out_size) {
    (void)in_sizes; (void)n_in; (void)out_size;
    const float* xyz = (const float*)d_in[0];
    float* out = (float*)d_out;
    fps_init<<<1, 32>>>();
    fps_kernel<<<BATCHES * NBLK, THREADS>>>(xyz, out);
}

// round 8
// speedup vs baseline: 1.4386x; 1.4386x over previous
#include <cuda_runtime.h>

// FurthestPoint sampling, B=16, N=65536, npoint=2048. sm_100a.
// 8 persistent blocks/batch, 512 thr x 16 pts/thread, packed f32x2 math.
// Inter-block sync: tag-in-slot, st.release.gpu.u64 store / ld.acquire.gpu.u64
// poll (strong ops only -> visibility guaranteed). Single round trip carries
// arrival + value + index. Double-buffered by iteration parity.

#define BATCHES 16
#define NPTS    65536
#define NPOINT  2048
#define NBLK    8
#define THREADS 512
#define PTS     16
#define PAIRS   (PTS / 2)
#define NWARP   (THREADS / 32)

// slot word: [63:32]=val bits, [31:16]=tag(j), [15:0]=idx. Padded to 32B.
__device__ unsigned long long g_slot[BATCHES][2][NBLK][4];

__global__ void fps_init() {
    const int n = BATCHES * 2 * NBLK;                  // 256
    if (threadIdx.x < n) {
        unsigned long long* p = &((unsigned long long*)g_slot)[threadIdx.x * 4];
        *p = ((unsigned long long)0xFFFFu) << 16;      // tag never matches any j
    }
}

__device__ __forceinline__ void st_release64(unsigned long long* p, unsigned long long v) {
    asm volatile("st.release.gpu.global.u64 [%0], %1;" :: "l"(p), "l"(v) : "memory");
}
__device__ __forceinline__ unsigned long long ld_acquire64(const unsigned long long* p) {
    unsigned long long v;
    asm volatile("ld.acquire.gpu.global.u64 %0, [%1];" : "=l"(v) : "l"(p) : "memory");
    return v;
}
__device__ __forceinline__ unsigned long long pack2(float lo, float hi) {
    unsigned long long r;
    asm("mov.b64 %0, {%1, %2};" : "=l"(r) : "f"(lo), "f"(hi));
    return r;
}
#define ADD2(d, a, b) asm("add.rn.f32x2 %0, %1, %2;" : "=l"(d) : "l"(a), "l"(b))
#define MUL2(d, a, b) asm("mul.rn.f32x2 %0, %1, %2;" : "=l"(d) : "l"(a), "l"(b))
#define FMA2(d, a, b, c) asm("fma.rn.f32x2 %0, %1, %2, %3;" : "=l"(d) : "l"(a), "l"(b), "l"(c))
#define UNPACK2(lo, hi, v) asm("mov.b64 {%0, %1}, %2;" : "=f"(lo), "=f"(hi) : "l"(v))

__global__ void __launch_bounds__(THREADS, 1)
fps_kernel(const float* __restrict__ xyz, float* __restrict__ out)
{
    const int b    = blockIdx.x / NBLK;
    const int blk  = blockIdx.x - b * NBLK;
    const int t    = threadIdx.x;
    const int lane = t & 31;
    const int wid  = t >> 5;

    const float* __restrict__ base = xyz + (size_t)b * NPTS * 3;
    float* __restrict__ out_idx = out;                              // (B, NPOINT) idx as float
    float* __restrict__ out_smp = out + (size_t)BATCHES * NPOINT;   // (B, 3, NPOINT)

    __shared__ unsigned s_wv[NWARP];
    __shared__ int      s_wi[NWARP];
    __shared__ float    s_p[3];

    // Register-resident points, packed two per u64.
    const int pbase = (blk * THREADS + t) * PTS;
    unsigned long long xp[PAIRS], yp[PAIRS], zp[PAIRS];
    float s[PTS];
#pragma unroll
    for (int i = 0; i < PAIRS; i++) {
        const float* q0 = base + (size_t)(pbase + 2 * i)     * 3;
        const float* q1 = base + (size_t)(pbase + 2 * i + 1) * 3;
        xp[i] = pack2(q0[0], q1[0]);
        yp[i] = pack2(q0[1], q1[1]);
        zp[i] = pack2(q0[2], q1[2]);
        s[2 * i] = 1e10f; s[2 * i + 1] = 1e10f;
    }

    float px = base[0], py = base[1], pz = base[2];
    if (blk == 0 && t == 0) {
        out_idx[(size_t)b * NPOINT] = 0.0f;
        out_smp[((size_t)b * 3 + 0) * NPOINT] = px;
        out_smp[((size_t)b * 3 + 1) * NPOINT] = py;
        out_smp[((size_t)b * 3 + 2) * NPOINT] = pz;
    }

    for (int j = 1; j < NPOINT; j++) {
        // ---- distance update, packed f32x2 (bit-exact: x+(-p) == x-p in rn) ----
        const unsigned long long npx = pack2(-px, -px);
        const unsigned long long npy = pack2(-py, -py);
        const unsigned long long npz = pack2(-pz, -pz);
#pragma unroll
        for (int i = 0; i < PAIRS; i++) {
            unsigned long long dx, dy, dz, dd;
            ADD2(dx, xp[i], npx);
            ADD2(dy, yp[i], npy);
            ADD2(dz, zp[i], npz);
            MUL2(dd, dx, dx);
            FMA2(dd, dy, dy, dd);
            FMA2(dd, dz, dz, dd);
            float lo, hi; UNPACK2(lo, hi, dd);
            s[2 * i]     = fminf(s[2 * i],     lo);
            s[2 * i + 1] = fminf(s[2 * i + 1], hi);
        }
        float t0 = fmaxf(fmaxf(s[0],  s[1]),  fmaxf(s[2],  s[3]));
        float t1 = fmaxf(fmaxf(s[4],  s[5]),  fmaxf(s[6],  s[7]));
        float t2 = fmaxf(fmaxf(s[8],  s[9]),  fmaxf(s[10], s[11]));
        float t3 = fmaxf(fmaxf(s[12], s[13]), fmaxf(s[14], s[15]));
        float m  = fmaxf(fmaxf(t0, t1), fmaxf(t2, t3));

        // ---- warp argmax: redux value, lowest lane == lowest index ----
        unsigned mu   = __float_as_uint(m);
        unsigned wmax = __reduce_max_sync(0xffffffffu, mu);
        unsigned ball = __ballot_sync(0xffffffffu, mu == wmax);
        int      src  = __ffs(ball) - 1;
        float    mf   = __uint_as_float(wmax);
        int kk = 0;
#pragma unroll
        for (int k = PTS - 1; k >= 0; k--)
            if (s[k] == mf) kk = k;                    // lowest k with max
        int idx = __shfl_sync(0xffffffffu, pbase + kk, src);

        if (lane == 0) { s_wv[wid] = wmax; s_wi[wid] = idx; }
        __syncthreads();

        if (wid == 0) {
            // ---- block argmax over 16 warp winners (lane order == index order) ----
            const int sl = lane & (NWARP - 1);
            unsigned v    = s_wv[sl];
            unsigned bmax = __reduce_max_sync(0xffffffffu, v);
            unsigned bb   = __ballot_sync(0xffffffffu, v == bmax);
            int      bsrc = __ffs(bb) - 1;
            int      widx = __shfl_sync(0xffffffffu, s_wi[bsrc], 0); // s_wi[bsrc] uniform read
            widx = s_wi[bsrc];

            const int buf = j & 1;
            unsigned long long (*slot)[4] = g_slot[b][buf];
            if (lane == 0)
                st_release64(&slot[blk][0],
                             ((unsigned long long)bmax << 32)
                             | ((unsigned long long)(j & 0xFFFF) << 16)
                             | (unsigned)(widx & 0xFFFF));

            // ---- single-RT poll: tag carries arrival, word carries data ----
            const int si = lane & (NBLK - 1);
            unsigned long long v64;
            do {
                v64 = ld_acquire64(&slot[si][0]);
            } while (!__all_sync(0xffffffffu, ((unsigned)(v64 >> 16) & 0xFFFFu) == (unsigned)j));

            // ---- cross-block argmax: two redux, no ballot needed ----
            unsigned val  = (unsigned)(v64 >> 32);
            unsigned gmax = __reduce_max_sync(0xffffffffu, val);
            unsigned cand = (val == gmax) ? (0xFFFFu - ((unsigned)v64 & 0xFFFFu)) : 0u;
            unsigned gk   = __reduce_max_sync(0xffffffffu, cand);
            int wi = (int)(0xFFFFu - gk);              // lowest idx among max-val slots

            const float* q = base + (size_t)wi * 3;    // uniform broadcast, L2-resident
            px = q[0]; py = q[1]; pz = q[2];
            if (lane == 0) {
                s_p[0] = px; s_p[1] = py; s_p[2] = pz;
                if (blk == 0) {
                    out_idx[(size_t)b * NPOINT + j] = (float)wi;
                    out_smp[((size_t)b * 3 + 0) * NPOINT + j] = px;
                    out_smp[((size_t)b * 3 + 1) * NPOINT + j] = py;
                    out_smp[((size_t)b * 3 + 2) * NPOINT + j] = pz;
                }
            }
        }
        __syncthreads();
        px = s_p[0]; py = s_p[1]; pz = s_p[2];
    }
}

extern "C" void kernel_launch(void* const* d_in, const int* in_sizes, int n_in,
                              void* d_out, int out_size) {
    (void)in_sizes; (void)n_in; (void)out_size;
    const float* xyz = (const float*)d_in[0];
    float* out = (float*)d_out;
    fps_init<<<1, 256>>>();
    fps_kernel<<<BATCHES * NBLK, THREADS>>>(xyz, out);
}